// round 15
// baseline (speedup 1.0000x reference)
#include <cuda_runtime.h>
#include <cuda_bf16.h>
#include <cuda_fp16.h>
#include <cstdint>
#include <math.h>

#define B 32
#define T_DEC 1024
#define T_SRC 2048
#define D 1024

// ============================================================================
// Scratch (device globals — no runtime alloc): fp16 planes for GEMM2
// ============================================================================
__device__ __align__(16) __half g_enc_h16[(size_t)B * T_SRC * D];
__device__ __align__(16) __half g_enc_l16[(size_t)B * T_SRC * D];
__device__ __align__(16) __half g_w16   [(size_t)B * T_DEC * T_SRC];

// ============================================================================
// helpers (compute_103-safe: sm_80+ PTX only)
// ============================================================================
__device__ __forceinline__ uint32_t smem_u32(const void* p) {
    uint32_t a;
    asm("{ .reg .u64 t; cvta.to.shared.u64 t, %1; cvt.u32.u64 %0, t; }" : "=r"(a) : "l"(p));
    return a;
}
__device__ __forceinline__ void cp16(uint32_t dst, const void* src) {
    asm volatile("cp.async.cg.shared.global [%0], [%1], 16;" :: "r"(dst), "l"(src));
}
#define CP_COMMIT() asm volatile("cp.async.commit_group;" ::: "memory")
#define CP_WAIT(N)  asm volatile("cp.async.wait_group %0;" :: "n"(N) : "memory")

__device__ __forceinline__ void ldsm_x4(uint32_t r[4], uint32_t addr) {
    asm volatile("ldmatrix.sync.aligned.m8n8.x4.shared.b16 {%0,%1,%2,%3}, [%4];"
                 : "=r"(r[0]), "=r"(r[1]), "=r"(r[2]), "=r"(r[3]) : "r"(addr));
}
__device__ __forceinline__ void ldsm_x4t(uint32_t r[4], uint32_t addr) {
    asm volatile("ldmatrix.sync.aligned.m8n8.x4.trans.shared.b16 {%0,%1,%2,%3}, [%4];"
                 : "=r"(r[0]), "=r"(r[1]), "=r"(r[2]), "=r"(r[3]) : "r"(addr));
}
__device__ __forceinline__ void mma_bf16(float d[4], const uint32_t a[4], const uint32_t b[2]) {
    asm volatile(
        "mma.sync.aligned.m16n8k16.row.col.f32.bf16.bf16.f32 "
        "{%0,%1,%2,%3}, {%4,%5,%6,%7}, {%8,%9}, {%0,%1,%2,%3};"
        : "+f"(d[0]), "+f"(d[1]), "+f"(d[2]), "+f"(d[3])
        : "r"(a[0]), "r"(a[1]), "r"(a[2]), "r"(a[3]), "r"(b[0]), "r"(b[1]));
}
__device__ __forceinline__ void mma_fp16(float d[4], const uint32_t a[4], const uint32_t b[2]) {
    asm volatile(
        "mma.sync.aligned.m16n8k16.row.col.f32.f16.f16.f32 "
        "{%0,%1,%2,%3}, {%4,%5,%6,%7}, {%8,%9}, {%0,%1,%2,%3};"
        : "+f"(d[0]), "+f"(d[1]), "+f"(d[2]), "+f"(d[3])
        : "r"(a[0]), "r"(a[1]), "r"(a[2]), "r"(a[3]), "r"(b[0]), "r"(b[1]));
}
// split fp32 -> (hi, lo) bf16 pairs, packed 2-at-a-time into b32
__device__ __forceinline__ void split2(float x0, float x1, uint32_t& h, uint32_t& l) {
    __nv_bfloat16 h0 = __float2bfloat16(x0);
    __nv_bfloat16 h1 = __float2bfloat16(x1);
    __nv_bfloat16 l0 = __float2bfloat16(x0 - __bfloat162float(h0));
    __nv_bfloat16 l1 = __float2bfloat16(x1 - __bfloat162float(h1));
    __nv_bfloat162 hp = __nv_bfloat162(h0, h1);
    __nv_bfloat162 lp = __nv_bfloat162(l0, l1);
    h = *(uint32_t*)&hp;
    l = *(uint32_t*)&lp;
}

// ============================================================================
// GEMM1 (scores): split-bf16 3-term, in-loop split, reg staging.
// C[m,n] = sum_k A[m,k]*B[n,k]; CTA 128x128, 128 thr, warp 64x64, BK=16, 2 CTA/SM.
// store_stage is interleaved mid-MMA to drain STS under tensor work.
// ============================================================================
#define BK 16
#define A_ST 24
#define REG_B 6144
#define OFF_AH 0
#define OFF_AL (REG_B)
#define OFF_BH (2 * REG_B)
#define OFF_BL (3 * REG_B)
#define STAGE  (4 * REG_B)
#define GEMM_SMEM (2 * STAGE)          // 49152

__global__ __launch_bounds__(128, 2)
void gemm1_scores(const float* __restrict__ A, const float* __restrict__ Bm,
                  float* __restrict__ C)
{
    extern __shared__ char dsm[];
    const uint32_t sbase = smem_u32(dsm);
    const int lda = D, ldb = D, ldc = T_SRC, KK = D;

    const int bz      = blockIdx.z;
    const int rowBase = blockIdx.y * 128;
    const int colBase = blockIdx.x * 128;

    const float* Ab = A  + (size_t)bz * T_DEC * D + (size_t)rowBase * lda;
    const float* Bb = Bm + (size_t)bz * T_SRC * D + (size_t)colBase * ldb;
    float*       Cb = C  + (size_t)bz * T_DEC * T_SRC;

    const int tid  = threadIdx.x;
    const int lane = tid & 31;
    const int wid  = tid >> 5;
    const int m0   = (wid >> 1) * 64;
    const int n0   = (wid & 1) * 64;

    float acc[4][8][4];
    #pragma unroll
    for (int i = 0; i < 4; i++)
        #pragma unroll
        for (int j = 0; j < 8; j++)
            #pragma unroll
            for (int r = 0; r < 4; r++) acc[i][j][r] = 0.f;

    const int nch = KK / BK;
    float4 ra[4], rb[4];

    auto load_regs = [&](int c) {
        const int kt = c * BK;
        #pragma unroll
        for (int q = 0; q < 4; q++) {
            const int f4 = tid + q * 128;
            const int row = f4 >> 2, kq = (f4 & 3) * 4;
            ra[q] = *(const float4*)(Ab + (size_t)row * lda + kt + kq);
        }
        #pragma unroll
        for (int q = 0; q < 4; q++) {
            const int f4 = tid + q * 128;
            const int row = f4 >> 2, kq = (f4 & 3) * 4;
            rb[q] = *(const float4*)(Bb + (size_t)row * ldb + kt + kq);
        }
    };
    auto store_stage = [&](int c) {
        char* st = dsm + (c & 1) * STAGE;
        #pragma unroll
        for (int q = 0; q < 4; q++) {
            const int f4 = tid + q * 128;
            const int row = f4 >> 2, kq = (f4 & 3) * 4;
            uint32_t h01, l01, h23, l23;
            split2(ra[q].x, ra[q].y, h01, l01);
            split2(ra[q].z, ra[q].w, h23, l23);
            const int off = (row * A_ST + kq) * 2;
            *(uint2*)(st + OFF_AH + off) = make_uint2(h01, h23);
            *(uint2*)(st + OFF_AL + off) = make_uint2(l01, l23);
        }
        #pragma unroll
        for (int q = 0; q < 4; q++) {
            const int f4 = tid + q * 128;
            const int row = f4 >> 2, kq = (f4 & 3) * 4;
            uint32_t h01, l01, h23, l23;
            split2(rb[q].x, rb[q].y, h01, l01);
            split2(rb[q].z, rb[q].w, h23, l23);
            const int off = (row * A_ST + kq) * 2;
            *(uint2*)(st + OFF_BH + off) = make_uint2(h01, h23);
            *(uint2*)(st + OFF_BL + off) = make_uint2(l01, l23);
        }
    };

    load_regs(0);
    store_stage(0);

    for (int c = 0; c < nch; c++) {
        __syncthreads();                       // stage c&1 ready; stage (c+1)&1 free
        if (c + 1 < nch) load_regs(c + 1);     // LDGs in flight under the MMAs

        const uint32_t stg = sbase + (c & 1) * STAGE;
        uint32_t ah[4][4], al[4][4];
        #pragma unroll
        for (int im = 0; im < 4; im++) {
            const uint32_t ad = stg + OFF_AH +
                ((m0 + im * 16 + (lane & 15)) * A_ST + ((lane >> 4) & 1) * 8) * 2;
            ldsm_x4(ah[im], ad);
            ldsm_x4(al[im], ad + (OFF_AL - OFF_AH));
        }

        auto do_p = [&](int p) {
            const int g = lane >> 3;
            uint32_t bh4[4], bl4[4];
            const int row = n0 + p * 16 + (g >> 1) * 8 + (lane & 7);
            const int kc  = (g & 1) * 8;
            const uint32_t bd = stg + OFF_BH + (row * A_ST + kc) * 2;
            ldsm_x4(bh4, bd);
            ldsm_x4(bl4, bd + (OFF_BL - OFF_BH));
            uint32_t bh[2][2] = {{bh4[0], bh4[1]}, {bh4[2], bh4[3]}};
            uint32_t bl[2][2] = {{bl4[0], bl4[1]}, {bl4[2], bl4[3]}};
            #pragma unroll
            for (int im = 0; im < 4; im++)
                #pragma unroll
                for (int j = 0; j < 2; j++) {
                    float* a = acc[im][2 * p + j];
                    mma_bf16(a, ah[im], bh[j]);
                    mma_bf16(a, ah[im], bl[j]);
                    mma_bf16(a, al[im], bh[j]);
                }
        };

        do_p(0); do_p(1); do_p(2);
        if (c + 1 < nch) store_stage(c + 1);   // STS drains under remaining MMAs
        do_p(3);
    }

    const int r  = lane >> 2;
    const int cp = (lane & 3) * 2;
    #pragma unroll
    for (int im = 0; im < 4; im++) {
        #pragma unroll
        for (int jn = 0; jn < 8; jn++) {
            const int row = rowBase + m0 + im * 16 + r;
            const int col = colBase + n0 + jn * 8 + cp;
            *(float2*)(Cb + (size_t)row * ldc + col)       = make_float2(acc[im][jn][0], acc[im][jn][1]);
            *(float2*)(Cb + (size_t)(row + 8) * ldc + col) = make_float2(acc[im][jn][2], acc[im][jn][3]);
        }
    }
}

// ============================================================================
// GEMM2 (context): fp16 2-term, pre-split operands, 3-stage cp.async ring,
// ONE barrier per chunk. C[m,d] = sum_s w[m,s] * (Vh+Vl)[s,d].
// CTA 128x128, 128 thr, warp 64x64, BK=32, 2 CTA/SM.
// ============================================================================
#define H_BK 32
#define H_A_ST 40                      // [128 m][32 k] fp16 + pad
#define H_B_ST 136                     // [32 k][128 n] fp16 + pad
#define H_OFF_A  0
#define H_OFF_BH 10240                 // 128*40*2
#define H_OFF_BL 18944                 // + 32*136*2
#define H_STAGE  27648                 // + 32*136*2
#define H_NSTG   3
#define H_SMEM   (H_NSTG * H_STAGE)    // 82944

__global__ __launch_bounds__(128, 2)
void gemm2_ctx(const __half* __restrict__ W, const __half* __restrict__ Vh,
               const __half* __restrict__ Vl, float* __restrict__ C)
{
    extern __shared__ char dsm[];
    const uint32_t sbase = smem_u32(dsm);
    const int lda = T_SRC, ldb = D, ldc = D, KK = T_SRC;

    const int bz      = blockIdx.z;
    const int rowBase = blockIdx.y * 128;
    const int colBase = blockIdx.x * 128;

    const __half* Ab  = W  + (size_t)bz * T_DEC * T_SRC + (size_t)rowBase * lda;
    const __half* Bbh = Vh + (size_t)bz * T_SRC * D + colBase;
    const __half* Bbl = Vl + (size_t)bz * T_SRC * D + colBase;
    float* const  Cb  = C  + (size_t)bz * T_DEC * D;

    const int tid  = threadIdx.x;
    const int lane = tid & 31;
    const int wid  = tid >> 5;
    const int m0   = (wid >> 1) * 64;
    const int n0   = (wid & 1) * 64;

    float acc[4][8][4];
    #pragma unroll
    for (int i = 0; i < 4; i++)
        #pragma unroll
        for (int j = 0; j < 8; j++)
            #pragma unroll
            for (int r = 0; r < 4; r++) acc[i][j][r] = 0.f;

    const int nch = KK / H_BK;

    auto issue_loads = [&](int c) {
        const uint32_t stu = sbase + (c % H_NSTG) * H_STAGE;
        const int kt = c * H_BK;
        #pragma unroll
        for (int q = 0; q < 4; q++) {          // A: [128][32] fp16, 512 x 16B
            const int ch  = tid + q * 128;
            const int row = ch >> 2, c16 = ch & 3;
            cp16(stu + H_OFF_A + row * (H_A_ST * 2) + c16 * 16,
                 Ab + (size_t)row * lda + kt + c16 * 8);
        }
        #pragma unroll
        for (int q = 0; q < 4; q++) {          // B: [32][128] fp16 x2 planes
            const int ch  = tid + q * 128;
            const int row = ch >> 4, c16 = ch & 15;
            const uint32_t d0 = row * (H_B_ST * 2) + c16 * 16;
            const size_t   so = (size_t)(kt + row) * ldb + c16 * 8;
            cp16(stu + H_OFF_BH + d0, Bbh + so);
            cp16(stu + H_OFF_BL + d0, Bbl + so);
        }
        CP_COMMIT();
    };

    issue_loads(0);
    if (nch > 1) issue_loads(1);

    for (int c = 0; c < nch; c++) {
        if (c + 1 < nch) { CP_WAIT(1); }       // stage c landed (c+1 may be in flight)
        else             { CP_WAIT(0); }
        __syncthreads();                       // data visible to all; stage (c+2)%3 free
        if (c + 2 < nch) issue_loads(c + 2);   // safe: all warps past chunk c-1 reads

        const uint32_t stg = sbase + (c % H_NSTG) * H_STAGE;
        #pragma unroll
        for (int ks = 0; ks < 2; ks++) {
            const int k0 = ks * 16;
            uint32_t aw[4][4];
            #pragma unroll
            for (int im = 0; im < 4; im++) {
                const uint32_t ad = stg + H_OFF_A +
                    ((m0 + im * 16 + (lane & 15)) * H_A_ST + k0 + ((lane >> 4) & 1) * 8) * 2;
                ldsm_x4(aw[im], ad);
            }
            #pragma unroll
            for (int p = 0; p < 4; p++) {
                const int g = lane >> 3;
                uint32_t bh4[4], bl4[4];
                const int row = k0 + (g & 1) * 8 + (lane & 7);
                const int col = n0 + p * 16 + (g >> 1) * 8;
                const uint32_t bd = stg + H_OFF_BH + (row * H_B_ST + col) * 2;
                ldsm_x4t(bh4, bd);
                ldsm_x4t(bl4, bd + (H_OFF_BL - H_OFF_BH));
                uint32_t bh[2][2] = {{bh4[0], bh4[1]}, {bh4[2], bh4[3]}};
                uint32_t bl[2][2] = {{bl4[0], bl4[1]}, {bl4[2], bl4[3]}};
                #pragma unroll
                for (int im = 0; im < 4; im++)
                    #pragma unroll
                    for (int j = 0; j < 2; j++) {
                        float* a = acc[im][2 * p + j];
                        mma_fp16(a, aw[im], bh[j]);   // w * V_hi
                        mma_fp16(a, aw[im], bl[j]);   // w * V_lo
                    }
            }
        }
    }

    const int r  = lane >> 2;
    const int cp = (lane & 3) * 2;
    #pragma unroll
    for (int im = 0; im < 4; im++) {
        #pragma unroll
        for (int jn = 0; jn < 8; jn++) {
            const int row = rowBase + m0 + im * 16 + r;
            const int col = colBase + n0 + jn * 8 + cp;
            *(float2*)(Cb + (size_t)row * ldc + col)       = make_float2(acc[im][jn][0], acc[im][jn][1]);
            *(float2*)(Cb + (size_t)(row + 8) * ldc + col) = make_float2(acc[im][jn][2], acc[im][jn][3]);
        }
    }
}

// ============================================================================
// enc fp32 -> fp16 hi/lo planes
// ============================================================================
__global__ __launch_bounds__(256)
void split_enc_h16(const float* __restrict__ x,
                   __half* __restrict__ hi, __half* __restrict__ lo)
{
    const size_t i = ((size_t)blockIdx.x * 256 + threadIdx.x) * 4;
    float4 v = *(const float4*)(x + i);
    __half h0 = __float2half(v.x), h1 = __float2half(v.y);
    __half h2 = __float2half(v.z), h3 = __float2half(v.w);
    __half l0 = __float2half(v.x - __half2float(h0));
    __half l1 = __float2half(v.y - __half2float(h1));
    __half l2 = __float2half(v.z - __half2float(h2));
    __half l3 = __float2half(v.w - __half2float(h3));
    __half2 hp0(h0, h1), hp1(h2, h3), lp0(l0, l1), lp1(l2, l3);
    *(uint2*)(hi + i) = make_uint2(*(uint32_t*)&hp0, *(uint32_t*)&hp1);
    *(uint2*)(lo + i) = make_uint2(*(uint32_t*)&lp0, *(uint32_t*)&lp1);
}

// ============================================================================
// Masked softmax, in place; also emits fp16 weights for GEMM2.
// ============================================================================
__device__ __forceinline__ float warpRedMax(float v) {
    #pragma unroll
    for (int o = 16; o > 0; o >>= 1) v = fmaxf(v, __shfl_xor_sync(0xffffffffu, v, o));
    return v;
}
__device__ __forceinline__ float warpRedSum(float v) {
    #pragma unroll
    for (int o = 16; o > 0; o >>= 1) v += __shfl_xor_sync(0xffffffffu, v, o);
    return v;
}

__global__ __launch_bounds__(256)
void softmax_kernel(float* __restrict__ S, const int* __restrict__ M,
                    __half* __restrict__ w16)
{
    __shared__ float red[8];
    const int row = blockIdx.x;
    const int b   = row / T_DEC;
    float* x = S + (size_t)row * T_SRC;
    const int* m = M + (size_t)b * T_SRC;
    __half* wr = w16 + (size_t)row * T_SRC;

    const int tid  = threadIdx.x;
    const int lane = tid & 31;
    const int wid  = tid >> 5;

    float v[8];
    float mx = -INFINITY;
    #pragma unroll
    for (int i = 0; i < 8; i++) {
        int s = tid + i * 256;
        float val = x[s];
        v[i] = (m[s] != 0) ? val : -INFINITY;
        mx = fmaxf(mx, v[i]);
    }
    mx = warpRedMax(mx);
    if (lane == 0) red[wid] = mx;
    __syncthreads();
    if (wid == 0) {
        float t = (lane < 8) ? red[lane] : -INFINITY;
        t = warpRedMax(t);
        if (lane == 0) red[0] = t;
    }
    __syncthreads();
    mx = red[0];

    float sum = 0.f;
    #pragma unroll
    for (int i = 0; i < 8; i++) {
        float e = __expf(v[i] - mx);
        v[i] = e;
        sum += e;
    }
    sum = warpRedSum(sum);
    __syncthreads();
    if (lane == 0) red[wid] = sum;
    __syncthreads();
    if (wid == 0) {
        float t = (lane < 8) ? red[lane] : 0.0f;
        t = warpRedSum(t);
        if (lane == 0) red[0] = t;
    }
    __syncthreads();
    const float inv = 1.0f / red[0];

    #pragma unroll
    for (int i = 0; i < 8; i++) {
        int s = tid + i * 256;
        float w = v[i] * inv;
        x[s] = w;
        wr[s] = __float2half(w);
    }
}

// ============================================================================
// Launch
// ============================================================================
extern "C" void kernel_launch(void* const* d_in, const int* in_sizes, int n_in,
                              void* d_out, int out_size)
{
    (void)in_sizes; (void)n_in; (void)out_size;
    const float* dec  = (const float*)d_in[0];   // [B, T_DEC, D]
    const float* enc  = (const float*)d_in[1];   // [B, T_SRC, D]
    const int*   mask = (const int*)d_in[2];     // [B, 1, T_SRC] bool -> int32

    float* ctx  = (float*)d_out;                              // [B, T_DEC, D]
    float* attn = (float*)d_out + (size_t)B * T_DEC * D;      // [B, T_DEC, T_SRC]

    void *ench, *encl, *w16;
    cudaGetSymbolAddress(&ench, g_enc_h16);
    cudaGetSymbolAddress(&encl, g_enc_l16);
    cudaGetSymbolAddress(&w16,  g_w16);

    cudaFuncSetAttribute(gemm1_scores,
                         cudaFuncAttributeMaxDynamicSharedMemorySize, GEMM_SMEM);
    cudaFuncSetAttribute(gemm2_ctx,
                         cudaFuncAttributeMaxDynamicSharedMemorySize, H_SMEM);

    // 1) enc -> fp16 hi/lo planes (one-time, off critical tensor path)
    split_enc_h16<<<(int)(((size_t)B * T_SRC * D) / 1024), 256>>>(
        enc, (__half*)ench, (__half*)encl);

    // 2) scores = dec x enc^T  (split-bf16, 3-term, in-loop split)
    gemm1_scores<<<dim3(T_SRC / 128, T_DEC / 128, B), 128, GEMM_SMEM>>>(
        dec, enc, attn);

    // 3) masked softmax in place + fp16 weights
    softmax_kernel<<<B * T_DEC, 256>>>(attn, mask, (__half*)w16);

    // 4) context = w16 x (Vh+Vl)  (fp16, 2-term, 3-stage cp.async)
    gemm2_ctx<<<dim3(D / 128, T_DEC / 128, B), 128, H_SMEM>>>(
        (const __half*)w16, (const __half*)ench, (const __half*)encl, ctx);
}

// round 16
// speedup vs baseline: 1.3887x; 1.3887x over previous
#include <cuda_runtime.h>
#include <cuda_bf16.h>
#include <cuda_fp16.h>
#include <cstdint>
#include <math.h>

#define B 32
#define T_DEC 1024
#define T_SRC 2048
#define D 1024

// ============================================================================
// Scratch (device globals — no runtime alloc): fp16 planes for GEMM2
// ============================================================================
__device__ __align__(16) __half g_enc_h16[(size_t)B * T_SRC * D];
__device__ __align__(16) __half g_enc_l16[(size_t)B * T_SRC * D];
__device__ __align__(16) __half g_w16   [(size_t)B * T_DEC * T_SRC];

// ============================================================================
// helpers (compute_103-safe: sm_80+ PTX only)
// ============================================================================
__device__ __forceinline__ uint32_t smem_u32(const void* p) {
    uint32_t a;
    asm("{ .reg .u64 t; cvta.to.shared.u64 t, %1; cvt.u32.u64 %0, t; }" : "=r"(a) : "l"(p));
    return a;
}
__device__ __forceinline__ void cp16(uint32_t dst, const void* src) {
    asm volatile("cp.async.cg.shared.global [%0], [%1], 16;" :: "r"(dst), "l"(src));
}
#define CP_COMMIT() asm volatile("cp.async.commit_group;" ::: "memory")
#define CP_WAIT(N)  asm volatile("cp.async.wait_group %0;" :: "n"(N) : "memory")

__device__ __forceinline__ void ldsm_x4(uint32_t r[4], uint32_t addr) {
    asm volatile("ldmatrix.sync.aligned.m8n8.x4.shared.b16 {%0,%1,%2,%3}, [%4];"
                 : "=r"(r[0]), "=r"(r[1]), "=r"(r[2]), "=r"(r[3]) : "r"(addr));
}
__device__ __forceinline__ void ldsm_x4t(uint32_t r[4], uint32_t addr) {
    asm volatile("ldmatrix.sync.aligned.m8n8.x4.trans.shared.b16 {%0,%1,%2,%3}, [%4];"
                 : "=r"(r[0]), "=r"(r[1]), "=r"(r[2]), "=r"(r[3]) : "r"(addr));
}
__device__ __forceinline__ void mma_bf16(float d[4], const uint32_t a[4], const uint32_t b[2]) {
    asm volatile(
        "mma.sync.aligned.m16n8k16.row.col.f32.bf16.bf16.f32 "
        "{%0,%1,%2,%3}, {%4,%5,%6,%7}, {%8,%9}, {%0,%1,%2,%3};"
        : "+f"(d[0]), "+f"(d[1]), "+f"(d[2]), "+f"(d[3])
        : "r"(a[0]), "r"(a[1]), "r"(a[2]), "r"(a[3]), "r"(b[0]), "r"(b[1]));
}
__device__ __forceinline__ void mma_fp16(float d[4], const uint32_t a[4], const uint32_t b[2]) {
    asm volatile(
        "mma.sync.aligned.m16n8k16.row.col.f32.f16.f16.f32 "
        "{%0,%1,%2,%3}, {%4,%5,%6,%7}, {%8,%9}, {%0,%1,%2,%3};"
        : "+f"(d[0]), "+f"(d[1]), "+f"(d[2]), "+f"(d[3])
        : "r"(a[0]), "r"(a[1]), "r"(a[2]), "r"(a[3]), "r"(b[0]), "r"(b[1]));
}
// split fp32 -> (hi, lo) bf16 pairs, packed 2-at-a-time into b32
__device__ __forceinline__ void split2(float x0, float x1, uint32_t& h, uint32_t& l) {
    __nv_bfloat16 h0 = __float2bfloat16(x0);
    __nv_bfloat16 h1 = __float2bfloat16(x1);
    __nv_bfloat16 l0 = __float2bfloat16(x0 - __bfloat162float(h0));
    __nv_bfloat16 l1 = __float2bfloat16(x1 - __bfloat162float(h1));
    __nv_bfloat162 hp = __nv_bfloat162(h0, h1);
    __nv_bfloat162 lp = __nv_bfloat162(l0, l1);
    h = *(uint32_t*)&hp;
    l = *(uint32_t*)&lp;
}

// CTA-wide valid-length of batch bz from the prefix mask (128 threads).
__device__ __forceinline__ int mask_length_128(const int* __restrict__ M, int bz,
                                               int tid, int lane, int wid) {
    __shared__ int lred[4];
    const int4* mrow = (const int4*)(M + (size_t)bz * T_SRC);
    int part = 0;
    #pragma unroll
    for (int q = 0; q < 4; q++) {               // 512 int4 over 128 threads
        int4 mv = mrow[tid + q * 128];
        part += (mv.x != 0) + (mv.y != 0) + (mv.z != 0) + (mv.w != 0);
    }
    #pragma unroll
    for (int o = 16; o > 0; o >>= 1) part += __shfl_xor_sync(0xffffffffu, part, o);
    if (lane == 0) lred[wid] = part;
    __syncthreads();
    return lred[0] + lred[1] + lred[2] + lred[3];
}

// ============================================================================
// GEMM1 (scores): split-bf16 3-term, in-loop split, reg staging (R14 structure).
// C[m,n] = sum_k A[m,k]*B[n,k]; CTA 128x128, 128 thr, warp 64x64, BK=16, 2 CTA/SM.
// CTAs whose entire column tile is masked (colBase >= L) exit immediately —
// softmax writes 0 weights there regardless of score values.
// ============================================================================
#define BK 16
#define A_ST 24
#define REG_B 6144
#define OFF_AH 0
#define OFF_AL (REG_B)
#define OFF_BH (2 * REG_B)
#define OFF_BL (3 * REG_B)
#define STAGE  (4 * REG_B)
#define GEMM_SMEM (2 * STAGE)          // 49152

__global__ __launch_bounds__(128, 2)
void gemm1_scores(const float* __restrict__ A, const float* __restrict__ Bm,
                  const int* __restrict__ M, float* __restrict__ C)
{
    extern __shared__ char dsm[];
    const uint32_t sbase = smem_u32(dsm);
    const int lda = D, ldb = D, ldc = T_SRC, KK = D;

    const int bz      = blockIdx.z;
    const int rowBase = blockIdx.y * 128;
    const int colBase = blockIdx.x * 128;

    const int tid  = threadIdx.x;
    const int lane = tid & 31;
    const int wid  = tid >> 5;

    const int L = mask_length_128(M, bz, tid, lane, wid);
    if (colBase >= L) return;               // fully masked tile: dead work

    const float* Ab = A  + (size_t)bz * T_DEC * D + (size_t)rowBase * lda;
    const float* Bb = Bm + (size_t)bz * T_SRC * D + (size_t)colBase * ldb;
    float*       Cb = C  + (size_t)bz * T_DEC * T_SRC;

    const int m0 = (wid >> 1) * 64;
    const int n0 = (wid & 1) * 64;

    float acc[4][8][4];
    #pragma unroll
    for (int i = 0; i < 4; i++)
        #pragma unroll
        for (int j = 0; j < 8; j++)
            #pragma unroll
            for (int r = 0; r < 4; r++) acc[i][j][r] = 0.f;

    const int nch = KK / BK;
    float4 ra[4], rb[4];

    auto load_regs = [&](int c) {
        const int kt = c * BK;
        #pragma unroll
        for (int q = 0; q < 4; q++) {
            const int f4 = tid + q * 128;
            const int row = f4 >> 2, kq = (f4 & 3) * 4;
            ra[q] = *(const float4*)(Ab + (size_t)row * lda + kt + kq);
        }
        #pragma unroll
        for (int q = 0; q < 4; q++) {
            const int f4 = tid + q * 128;
            const int row = f4 >> 2, kq = (f4 & 3) * 4;
            rb[q] = *(const float4*)(Bb + (size_t)row * ldb + kt + kq);
        }
    };
    auto store_stage = [&](int c) {
        char* st = dsm + (c & 1) * STAGE;
        #pragma unroll
        for (int q = 0; q < 4; q++) {
            const int f4 = tid + q * 128;
            const int row = f4 >> 2, kq = (f4 & 3) * 4;
            uint32_t h01, l01, h23, l23;
            split2(ra[q].x, ra[q].y, h01, l01);
            split2(ra[q].z, ra[q].w, h23, l23);
            const int off = (row * A_ST + kq) * 2;
            *(uint2*)(st + OFF_AH + off) = make_uint2(h01, h23);
            *(uint2*)(st + OFF_AL + off) = make_uint2(l01, l23);
        }
        #pragma unroll
        for (int q = 0; q < 4; q++) {
            const int f4 = tid + q * 128;
            const int row = f4 >> 2, kq = (f4 & 3) * 4;
            uint32_t h01, l01, h23, l23;
            split2(rb[q].x, rb[q].y, h01, l01);
            split2(rb[q].z, rb[q].w, h23, l23);
            const int off = (row * A_ST + kq) * 2;
            *(uint2*)(st + OFF_BH + off) = make_uint2(h01, h23);
            *(uint2*)(st + OFF_BL + off) = make_uint2(l01, l23);
        }
    };

    load_regs(0);
    store_stage(0);

    for (int c = 0; c < nch; c++) {
        __syncthreads();
        if (c + 1 < nch) load_regs(c + 1);

        const uint32_t stg = sbase + (c & 1) * STAGE;
        uint32_t ah[4][4], al[4][4];
        #pragma unroll
        for (int im = 0; im < 4; im++) {
            const uint32_t ad = stg + OFF_AH +
                ((m0 + im * 16 + (lane & 15)) * A_ST + ((lane >> 4) & 1) * 8) * 2;
            ldsm_x4(ah[im], ad);
            ldsm_x4(al[im], ad + (OFF_AL - OFF_AH));
        }
        #pragma unroll
        for (int p = 0; p < 4; p++) {
            const int g = lane >> 3;
            uint32_t bh4[4], bl4[4];
            const int row = n0 + p * 16 + (g >> 1) * 8 + (lane & 7);
            const int kc  = (g & 1) * 8;
            const uint32_t bd = stg + OFF_BH + (row * A_ST + kc) * 2;
            ldsm_x4(bh4, bd);
            ldsm_x4(bl4, bd + (OFF_BL - OFF_BH));
            uint32_t bh[2][2] = {{bh4[0], bh4[1]}, {bh4[2], bh4[3]}};
            uint32_t bl[2][2] = {{bl4[0], bl4[1]}, {bl4[2], bl4[3]}};
            #pragma unroll
            for (int im = 0; im < 4; im++)
                #pragma unroll
                for (int j = 0; j < 2; j++) {
                    float* a = acc[im][2 * p + j];
                    mma_bf16(a, ah[im], bh[j]);
                    mma_bf16(a, ah[im], bl[j]);
                    mma_bf16(a, al[im], bh[j]);
                }
        }

        if (c + 1 < nch) store_stage(c + 1);
    }

    const int r  = lane >> 2;
    const int cp = (lane & 3) * 2;
    #pragma unroll
    for (int im = 0; im < 4; im++) {
        #pragma unroll
        for (int jn = 0; jn < 8; jn++) {
            const int row = rowBase + m0 + im * 16 + r;
            const int col = colBase + n0 + jn * 8 + cp;
            *(float2*)(Cb + (size_t)row * ldc + col)       = make_float2(acc[im][jn][0], acc[im][jn][1]);
            *(float2*)(Cb + (size_t)(row + 8) * ldc + col) = make_float2(acc[im][jn][2], acc[im][jn][3]);
        }
    }
}

// ============================================================================
// GEMM2 (context): fp16 2-term, pre-split operands, 2-stage cp.async (R14),
// k-loop truncated at ceil(L/BK): w is exactly 0 for s >= L.
// ============================================================================
#define H_BK 32
#define H_A_ST 40                      // [128 m][32 k] fp16 + pad
#define H_B_ST 136                     // [32 k][128 n] fp16 + pad
#define H_OFF_A  0
#define H_OFF_BH 10240                 // 128*40*2
#define H_OFF_BL 18944                 // + 32*136*2
#define H_STAGE  27648                 // + 32*136*2
#define H_SMEM   (2 * H_STAGE)         // 55296

__global__ __launch_bounds__(128, 2)
void gemm2_ctx(const __half* __restrict__ W, const __half* __restrict__ Vh,
               const __half* __restrict__ Vl, const int* __restrict__ M,
               float* __restrict__ C)
{
    extern __shared__ char dsm[];
    const uint32_t sbase = smem_u32(dsm);
    const int lda = T_SRC, ldb = D, ldc = D;

    const int bz      = blockIdx.z;
    const int rowBase = blockIdx.y * 128;
    const int colBase = blockIdx.x * 128;

    const int tid  = threadIdx.x;
    const int lane = tid & 31;
    const int wid  = tid >> 5;

    const int L   = mask_length_128(M, bz, tid, lane, wid);
    const int nch = (L + H_BK - 1) / H_BK;      // chunks beyond L are all-zero w

    const __half* Ab  = W  + (size_t)bz * T_DEC * T_SRC + (size_t)rowBase * lda;
    const __half* Bbh = Vh + (size_t)bz * T_SRC * D + colBase;
    const __half* Bbl = Vl + (size_t)bz * T_SRC * D + colBase;
    float* const  Cb  = C  + (size_t)bz * T_DEC * D;

    const int m0 = (wid >> 1) * 64;
    const int n0 = (wid & 1) * 64;

    float acc[4][8][4];
    #pragma unroll
    for (int i = 0; i < 4; i++)
        #pragma unroll
        for (int j = 0; j < 8; j++)
            #pragma unroll
            for (int r = 0; r < 4; r++) acc[i][j][r] = 0.f;

    auto issue_loads = [&](int c) {
        const uint32_t stu = sbase + (c & 1) * H_STAGE;
        const int kt = c * H_BK;
        #pragma unroll
        for (int q = 0; q < 4; q++) {          // A: [128][32] fp16, 512 x 16B
            const int ch  = tid + q * 128;
            const int row = ch >> 2, c16 = ch & 3;
            cp16(stu + H_OFF_A + row * (H_A_ST * 2) + c16 * 16,
                 Ab + (size_t)row * lda + kt + c16 * 8);
        }
        #pragma unroll
        for (int q = 0; q < 4; q++) {          // B: [32][128] fp16 x2 planes
            const int ch  = tid + q * 128;
            const int row = ch >> 4, c16 = ch & 15;
            const uint32_t d0 = row * (H_B_ST * 2) + c16 * 16;
            const size_t   so = (size_t)(kt + row) * ldb + c16 * 8;
            cp16(stu + H_OFF_BH + d0, Bbh + so);
            cp16(stu + H_OFF_BL + d0, Bbl + so);
        }
        CP_COMMIT();
    };

    issue_loads(0);

    for (int c = 0; c < nch; c++) {
        if (c + 1 < nch) { issue_loads(c + 1); CP_WAIT(1); }
        else             { CP_WAIT(0); }
        __syncthreads();

        const uint32_t stg = sbase + (c & 1) * H_STAGE;
        #pragma unroll
        for (int ks = 0; ks < 2; ks++) {
            const int k0 = ks * 16;
            uint32_t aw[4][4];
            #pragma unroll
            for (int im = 0; im < 4; im++) {
                const uint32_t ad = stg + H_OFF_A +
                    ((m0 + im * 16 + (lane & 15)) * H_A_ST + k0 + ((lane >> 4) & 1) * 8) * 2;
                ldsm_x4(aw[im], ad);
            }
            #pragma unroll
            for (int p = 0; p < 4; p++) {
                const int g = lane >> 3;
                uint32_t bh4[4], bl4[4];
                const int row = k0 + (g & 1) * 8 + (lane & 7);
                const int col = n0 + p * 16 + (g >> 1) * 8;
                const uint32_t bd = stg + H_OFF_BH + (row * H_B_ST + col) * 2;
                ldsm_x4t(bh4, bd);
                ldsm_x4t(bl4, bd + (H_OFF_BL - H_OFF_BH));
                uint32_t bh[2][2] = {{bh4[0], bh4[1]}, {bh4[2], bh4[3]}};
                uint32_t bl[2][2] = {{bl4[0], bl4[1]}, {bl4[2], bl4[3]}};
                #pragma unroll
                for (int im = 0; im < 4; im++)
                    #pragma unroll
                    for (int j = 0; j < 2; j++) {
                        float* a = acc[im][2 * p + j];
                        mma_fp16(a, aw[im], bh[j]);   // w * V_hi
                        mma_fp16(a, aw[im], bl[j]);   // w * V_lo
                    }
            }
        }
        __syncthreads();
    }

    const int r  = lane >> 2;
    const int cp = (lane & 3) * 2;
    #pragma unroll
    for (int im = 0; im < 4; im++) {
        #pragma unroll
        for (int jn = 0; jn < 8; jn++) {
            const int row = rowBase + m0 + im * 16 + r;
            const int col = colBase + n0 + jn * 8 + cp;
            *(float2*)(Cb + (size_t)row * ldc + col)       = make_float2(acc[im][jn][0], acc[im][jn][1]);
            *(float2*)(Cb + (size_t)(row + 8) * ldc + col) = make_float2(acc[im][jn][2], acc[im][jn][3]);
        }
    }
}

// ============================================================================
// enc fp32 -> fp16 hi/lo planes
// ============================================================================
__global__ __launch_bounds__(256)
void split_enc_h16(const float* __restrict__ x,
                   __half* __restrict__ hi, __half* __restrict__ lo)
{
    const size_t i = ((size_t)blockIdx.x * 256 + threadIdx.x) * 4;
    float4 v = *(const float4*)(x + i);
    __half h0 = __float2half(v.x), h1 = __float2half(v.y);
    __half h2 = __float2half(v.z), h3 = __float2half(v.w);
    __half l0 = __float2half(v.x - __half2float(h0));
    __half l1 = __float2half(v.y - __half2float(h1));
    __half l2 = __float2half(v.z - __half2float(h2));
    __half l3 = __float2half(v.w - __half2float(h3));
    __half2 hp0(h0, h1), hp1(h2, h3), lp0(l0, l1), lp1(l2, l3);
    *(uint2*)(hi + i) = make_uint2(*(uint32_t*)&hp0, *(uint32_t*)&hp1);
    *(uint2*)(lo + i) = make_uint2(*(uint32_t*)&lp0, *(uint32_t*)&lp1);
}

// ============================================================================
// Masked softmax, in place; also emits fp16 weights for GEMM2.
// ============================================================================
__device__ __forceinline__ float warpRedMax(float v) {
    #pragma unroll
    for (int o = 16; o > 0; o >>= 1) v = fmaxf(v, __shfl_xor_sync(0xffffffffu, v, o));
    return v;
}
__device__ __forceinline__ float warpRedSum(float v) {
    #pragma unroll
    for (int o = 16; o > 0; o >>= 1) v += __shfl_xor_sync(0xffffffffu, v, o);
    return v;
}

__global__ __launch_bounds__(256)
void softmax_kernel(float* __restrict__ S, const int* __restrict__ M,
                    __half* __restrict__ w16)
{
    __shared__ float red[8];
    const int row = blockIdx.x;
    const int b   = row / T_DEC;
    float* x = S + (size_t)row * T_SRC;
    const int* m = M + (size_t)b * T_SRC;
    __half* wr = w16 + (size_t)row * T_SRC;

    const int tid  = threadIdx.x;
    const int lane = tid & 31;
    const int wid  = tid >> 5;

    float v[8];
    float mx = -INFINITY;
    #pragma unroll
    for (int i = 0; i < 8; i++) {
        int s = tid + i * 256;
        float val = x[s];
        v[i] = (m[s] != 0) ? val : -INFINITY;
        mx = fmaxf(mx, v[i]);
    }
    mx = warpRedMax(mx);
    if (lane == 0) red[wid] = mx;
    __syncthreads();
    if (wid == 0) {
        float t = (lane < 8) ? red[lane] : -INFINITY;
        t = warpRedMax(t);
        if (lane == 0) red[0] = t;
    }
    __syncthreads();
    mx = red[0];

    float sum = 0.f;
    #pragma unroll
    for (int i = 0; i < 8; i++) {
        float e = __expf(v[i] - mx);
        v[i] = e;
        sum += e;
    }
    sum = warpRedSum(sum);
    __syncthreads();
    if (lane == 0) red[wid] = sum;
    __syncthreads();
    if (wid == 0) {
        float t = (lane < 8) ? red[lane] : 0.0f;
        t = warpRedSum(t);
        if (lane == 0) red[0] = t;
    }
    __syncthreads();
    const float inv = 1.0f / red[0];

    #pragma unroll
    for (int i = 0; i < 8; i++) {
        int s = tid + i * 256;
        float w = v[i] * inv;
        x[s] = w;
        wr[s] = __float2half(w);
    }
}

// ============================================================================
// Launch
// ============================================================================
extern "C" void kernel_launch(void* const* d_in, const int* in_sizes, int n_in,
                              void* d_out, int out_size)
{
    (void)in_sizes; (void)n_in; (void)out_size;
    const float* dec  = (const float*)d_in[0];   // [B, T_DEC, D]
    const float* enc  = (const float*)d_in[1];   // [B, T_SRC, D]
    const int*   mask = (const int*)d_in[2];     // [B, 1, T_SRC] bool -> int32

    float* ctx  = (float*)d_out;                              // [B, T_DEC, D]
    float* attn = (float*)d_out + (size_t)B * T_DEC * D;      // [B, T_DEC, T_SRC]

    void *ench, *encl, *w16;
    cudaGetSymbolAddress(&ench, g_enc_h16);
    cudaGetSymbolAddress(&encl, g_enc_l16);
    cudaGetSymbolAddress(&w16,  g_w16);

    cudaFuncSetAttribute(gemm1_scores,
                         cudaFuncAttributeMaxDynamicSharedMemorySize, GEMM_SMEM);
    cudaFuncSetAttribute(gemm2_ctx,
                         cudaFuncAttributeMaxDynamicSharedMemorySize, H_SMEM);

    // 1) enc -> fp16 hi/lo planes (one-time, off critical tensor path)
    split_enc_h16<<<(int)(((size_t)B * T_SRC * D) / 1024), 256>>>(
        enc, (__half*)ench, (__half*)encl);

    // 2) scores = dec x enc^T  (split-bf16 3-term; fully-masked tiles skipped)
    gemm1_scores<<<dim3(T_SRC / 128, T_DEC / 128, B), 128, GEMM_SMEM>>>(
        dec, enc, mask, attn);

    // 3) masked softmax in place + fp16 weights (writes 0 for masked cols)
    softmax_kernel<<<B * T_DEC, 256>>>(attn, mask, (__half*)w16);

    // 4) context = w16 x (Vh+Vl)  (fp16 2-term; k-loop truncated at L_b)
    gemm2_ctx<<<dim3(D / 128, T_DEC / 128, B), 128, H_SMEM>>>(
        (const __half*)w16, (const __half*)ench, (const __half*)encl, mask, ctx);
}